// round 1
// baseline (speedup 1.0000x reference)
#include <cuda_runtime.h>

// MultiIndexSelect: out[to_k[i]] = mat_k[from_k[i]], k=0..2, L rows each, D=64 f32.
// Row = 256 bytes = 16 float4. 16 lanes per row, 2 rows per warp.
// Pure HBM-bound streaming gather/scatter; goal is full coalescing + enough
// parallelism to saturate ~8 TB/s HBM3e.

static constexpr int L_CONST = 400000;

__global__ __launch_bounds__(256) void multi_index_select_kernel(
    const float4* __restrict__ m0,
    const float4* __restrict__ m1,
    const float4* __restrict__ m2,
    const int* __restrict__ f0,
    const int* __restrict__ f1,
    const int* __restrict__ f2,
    const int* __restrict__ t0,
    const int* __restrict__ t1,
    const int* __restrict__ t2,
    float4* __restrict__ out,
    int L)
{
    // One "slot" = one float4 of one output row. 16 slots per row.
    unsigned tid = blockIdx.x * blockDim.x + threadIdx.x;   // < 3*L*16 = 19.2M, fits u32
    unsigned total = 3u * (unsigned)L * 16u;
    if (tid >= total) return;

    unsigned row  = tid >> 4;   // global row index in [0, 3L)
    unsigned lane = tid & 15u;  // float4 index within the row

    const float4* __restrict__ mat;
    int src, dst;
    if (row < (unsigned)L) {
        mat = m0; src = __ldg(&f0[row]);          dst = __ldg(&t0[row]);
    } else if (row < 2u * (unsigned)L) {
        unsigned r = row - (unsigned)L;
        mat = m1; src = __ldg(&f1[r]);            dst = __ldg(&t1[r]);
    } else {
        unsigned r = row - 2u * (unsigned)L;
        mat = m2; src = __ldg(&f2[r]);            dst = __ldg(&t2[r]);
    }

    out[(size_t)dst * 16u + lane] = __ldg(&mat[(size_t)src * 16u + lane]);
}

extern "C" void kernel_launch(void* const* d_in, const int* in_sizes, int n_in,
                              void* d_out, int out_size)
{
    const float4* m0 = (const float4*)d_in[0];
    const float4* m1 = (const float4*)d_in[1];
    const float4* m2 = (const float4*)d_in[2];
    const int* f0 = (const int*)d_in[3];
    const int* f1 = (const int*)d_in[4];
    const int* f2 = (const int*)d_in[5];
    const int* t0 = (const int*)d_in[6];
    const int* t1 = (const int*)d_in[7];
    const int* t2 = (const int*)d_in[8];

    int L = in_sizes[3];          // length of from0 (should be 400000)
    (void)L_CONST;

    unsigned total = 3u * (unsigned)L * 16u;   // one thread per float4 slot
    int threads = 256;
    unsigned blocks = (total + threads - 1) / threads;

    multi_index_select_kernel<<<blocks, threads>>>(
        m0, m1, m2, f0, f1, f2, t0, t1, t2, (float4*)d_out, L);
}

// round 4
// speedup vs baseline: 1.2392x; 1.2392x over previous
#include <cuda_runtime.h>

// MultiIndexSelect: out[to_k[i]] = mat_k[from_k[i]], k=0..2, L=400000 rows each,
// D=64 f32. Row = 256 B = 16 float4 slots. UNROLL=4 slots per thread, all index
// loads + gathers batched before stores to raise MLP (R1: DRAM=54.7%, MLP=1,
// latency-bound). .cs on bulk data (one-touch), default caching on indices
// (each index word reused by 16 threads).

static constexpr int UNROLL = 4;

__global__ __launch_bounds__(256) void multi_index_select_kernel(
    const float4* __restrict__ m0,
    const float4* __restrict__ m1,
    const float4* __restrict__ m2,
    const int* __restrict__ f0,
    const int* __restrict__ f1,
    const int* __restrict__ f2,
    const int* __restrict__ t0,
    const int* __restrict__ t1,
    const int* __restrict__ t2,
    float4* __restrict__ out,
    int L)
{
    const unsigned total = 3u * (unsigned)L * 16u;     // 19.2M slots
    const unsigned base  = blockIdx.x * (blockDim.x * UNROLL) + threadIdx.x;

    float4   val[UNROLL];
    unsigned dslot[UNROLL];
    bool     ok[UNROLL];

    #pragma unroll
    for (int u = 0; u < UNROLL; u++) {
        unsigned tid = base + u * blockDim.x;
        ok[u] = (tid < total);
        unsigned row  = tid >> 4;
        unsigned lane = tid & 15u;
        if (ok[u]) {
            const float4* __restrict__ mat;
            int src, dst;
            if (row < (unsigned)L) {
                mat = m0; src = __ldg(&f0[row]);        dst = __ldg(&t0[row]);
            } else if (row < 2u * (unsigned)L) {
                unsigned r = row - (unsigned)L;
                mat = m1; src = __ldg(&f1[r]);          dst = __ldg(&t1[r]);
            } else {
                unsigned r = row - 2u * (unsigned)L;
                mat = m2; src = __ldg(&f2[r]);          dst = __ldg(&t2[r]);
            }
            dslot[u] = (unsigned)dst * 16u + lane;
            val[u]   = __ldcs(&mat[(size_t)src * 16u + lane]);
        }
    }

    #pragma unroll
    for (int u = 0; u < UNROLL; u++) {
        if (ok[u]) __stcs(&out[dslot[u]], val[u]);
    }
}

extern "C" void kernel_launch(void* const* d_in, const int* in_sizes, int n_in,
                              void* d_out, int out_size)
{
    const float4* m0 = (const float4*)d_in[0];
    const float4* m1 = (const float4*)d_in[1];
    const float4* m2 = (const float4*)d_in[2];
    const int* f0 = (const int*)d_in[3];
    const int* f1 = (const int*)d_in[4];
    const int* f2 = (const int*)d_in[5];
    const int* t0 = (const int*)d_in[6];
    const int* t1 = (const int*)d_in[7];
    const int* t2 = (const int*)d_in[8];

    int L = in_sizes[3];                                // 400000
    unsigned total = 3u * (unsigned)L * 16u;
    int threads = 256;
    unsigned per_block = threads * UNROLL;
    unsigned blocks = (total + per_block - 1) / per_block;

    multi_index_select_kernel<<<blocks, threads>>>(
        m0, m1, m2, f0, f1, f2, t0, t1, t2, (float4*)d_out, L);
}